// round 15
// baseline (speedup 1.0000x reference)
#include <cuda_runtime.h>
#include <math.h>

// Problem constants
#define BB 8
#define NN 2048
#define PTS (BB*NN)      // 16384
#define DD 64
#define KK 8
#define LV 3
#define H1 256
#define H2 128
#define PTB 32           // points per k_fuse block
#define KPT 32           // points per knn block
#define NKNNB (PTS/KPT)  // 512 knn blocks
#define NPREPB 256       // prep blocks (64 pts each)

// Scratch (device globals; no allocation allowed)
__device__ float g_A  [PTS*DD];
__device__ float g_Bf [PTS*DD];
__device__ float g_fw [PTS*LV];
__device__ int   g_idx[PTS*KK];

__device__ __forceinline__ float leaky(float v){ return v > 0.f ? v : 0.2f*v; }

__device__ __forceinline__ unsigned long long ffma2(unsigned long long a, unsigned long long b, unsigned long long c){
    asm("fma.rn.f32x2 %0, %1, %2, %0;" : "+l"(c) : "l"(a), "l"(b));
    return c;
}
__device__ __forceinline__ unsigned long long pack2(float w){
    unsigned long long r;
    asm("mov.b64 %0, {%1, %1};" : "=l"(r) : "f"(w));
    return r;
}

// Branchless sorted-8 insert: r[s] = min(b[s], max(b[s-1], e)).
#define VAL_INS8(B0,B1,B2,B3,B4,B5,B6,B7,E)            \
    {                                                  \
        float t0 = fminf(B0, E);                       \
        float t1 = fminf(B1, fmaxf(B0, E));            \
        float t2 = fminf(B2, fmaxf(B1, E));            \
        float t3 = fminf(B3, fmaxf(B2, E));            \
        float t4 = fminf(B4, fmaxf(B3, E));            \
        float t5 = fminf(B5, fmaxf(B4, E));            \
        float t6 = fminf(B6, fmaxf(B5, E));            \
        float t7 = fminf(B7, fmaxf(B6, E));            \
        B0=t0; B1=t1; B2=t2; B3=t3; B4=t4; B5=t5; B6=t6; B7=t7; \
    }

// ---------------------------------------------------------------------------
// K1 (merged): blocks [0, NKNNB) = KNN path; [NKNNB, NKNNB+NPREPB) = prep path.
// (proven R14 code, ~54us measured for both stages overlapped)
// ---------------------------------------------------------------------------
__global__ void __launch_bounds__(256)
k_pk(const float* __restrict__ x,
     const float* __restrict__ W1, const float* __restrict__ b1,
     const float* __restrict__ g1, const float* __restrict__ be1,
     const float* __restrict__ W2, const float* __restrict__ b2,
     const float* __restrict__ Ws1, const float* __restrict__ bs1,
     const float* __restrict__ Ws2, const float* __restrict__ bs2)
{
    extern __shared__ float sm[];
    const int tid = threadIdx.x;

    if (blockIdx.x < NKNNB) {
        // =================== KNN path (256 threads, 32 pts, 8 splits) =======
        float4* xsh = (float4*)sm;             // [2048] float4 = 8192 floats
        float*  mk  = sm + 8192;               // [32][65] = 2080

        const int kb  = blockIdx.x;
        const int b   = kb >> 6;               // 64 blocks per batch
        const int pl0 = (kb & 63) * KPT;

        for (int j = tid; j < NN; j += 256) {
            const float* xp = x + (b*NN + j)*3;
            float x0 = xp[0], x1 = xp[1], x2 = xp[2];
            xsh[j] = make_float4(x0, x1, x2, fmaf(x2, x2, fmaf(x1, x1, x0*x0)));
        }
        __syncthreads();

        const int pt = tid & 31, split = tid >> 5;
        float4 xi = xsh[pl0 + pt];
        const float ax = -2.f*xi.x, ay = -2.f*xi.y, az = -2.f*xi.z;
        const float bias = xi.w;
        const int j0 = split * 256;

        float b0=3.4e38f,b1r=3.4e38f,b2r=3.4e38f,b3=3.4e38f,
              b4=3.4e38f,b5=3.4e38f,b6=3.4e38f,b7=3.4e38f;
        #pragma unroll 4
        for (int j = j0; j < j0 + 256; j++) {
            float4 xj = xsh[j];
            float d2 = fmaf(xj.x, ax, fmaf(xj.y, ay, fmaf(xj.z, az, xj.w))) + bias;
            unsigned kbits = (__float_as_uint(d2) & 0xFFFFF800u) | (unsigned)j;
            float key = __uint_as_float(kbits);
            if (key < b7) VAL_INS8(b0,b1r,b2r,b3,b4,b5,b6,b7,key);
        }
        {
            float* mrow = mk + pt*65 + split*8;
            mrow[0]=b0; mrow[1]=b1r; mrow[2]=b2r; mrow[3]=b3;
            mrow[4]=b4; mrow[5]=b5; mrow[6]=b6; mrow[7]=b7;
        }
        __syncthreads();

        if (tid < KPT) {
            float s0=3.4e38f,s1=3.4e38f,s2=3.4e38f,s3=3.4e38f,
                  s4=3.4e38f,s5=3.4e38f,s6=3.4e38f,s7=3.4e38f;
            #pragma unroll
            for (int c = 0; c < 64; c++) {
                float v = mk[tid*65 + c];
                if (v < s7) VAL_INS8(s0,s1,s2,s3,s4,s5,s6,s7,v);
            }
            int gp = b*NN + pl0 + tid;
            g_idx[gp*8 + 0] = (int)(__float_as_uint(s0) & 0x7FFu);
            g_idx[gp*8 + 1] = (int)(__float_as_uint(s1) & 0x7FFu);
            g_idx[gp*8 + 2] = (int)(__float_as_uint(s2) & 0x7FFu);
            g_idx[gp*8 + 3] = (int)(__float_as_uint(s3) & 0x7FFu);
            g_idx[gp*8 + 4] = (int)(__float_as_uint(s4) & 0x7FFu);
            g_idx[gp*8 + 5] = (int)(__float_as_uint(s5) & 0x7FFu);
            g_idx[gp*8 + 6] = (int)(__float_as_uint(s6) & 0x7FFu);
            g_idx[gp*8 + 7] = (int)(__float_as_uint(s7) & 0x7FFu);
        }
        return;
    }

    // ======================= prep path (verbatim) ===========================
    float* W2s   = sm;               // 8192
    float* featS = W2s + 8192;       // 64*65 = 4160
    float* ssS   = featS + 4160;     // 4096
    float* W1s   = ssS + 4096;       // 192
    float* Ws1s  = W1s + 192;        // 192
    float* Ws2s  = Ws1s + 192;       // 192
    float* b1v   = Ws2s + 192;       // 64
    float* g1v   = b1v + 64;
    float* be1v  = g1v + 64;
    float* b2v   = be1v + 64;
    float* bs1v  = b2v + 64;
    float* bs2v  = bs1v + 64;        // 4
    float* xs    = bs2v + 4;         // 192

    const int p0 = (blockIdx.x - NKNNB) * 64;

    for (int i = tid; i < 8192; i += 256) W2s[i] = W2[i];
    for (int i = tid; i < 192; i += 256) { W1s[i] = W1[i]; Ws1s[i] = Ws1[i]; Ws2s[i] = Ws2[i]; xs[i] = x[p0*3 + i]; }
    if (tid < 64) { b1v[tid]=b1[tid]; g1v[tid]=g1[tid]; be1v[tid]=be1[tid]; b2v[tid]=b2[tid]; bs1v[tid]=bs1[tid]; }
    if (tid < 3)  bs2v[tid] = bs2[tid];
    __syncthreads();

    for (int i = tid; i < 4096; i += 256) {
        int pt = i >> 6, d = i & 63;
        float x0 = xs[pt*3], x1 = xs[pt*3+1], x2 = xs[pt*3+2];
        float f = fmaf(x2, W1s[128+d], fmaf(x1, W1s[64+d], fmaf(x0, W1s[d], b1v[d])));
        f = fmaf(f, g1v[d], be1v[d]);
        featS[pt*65 + d] = leaky(f);
        float s = fmaf(x2, Ws1s[128+d], fmaf(x1, Ws1s[64+d], fmaf(x0, Ws1s[d], bs1v[d])));
        ssS[pt*64 + d] = s > 0.f ? s : 0.f;
    }
    __syncthreads();

    if (tid < 192) {
        int pt = tid / 3, l = tid - pt*3;
        float s = bs2v[l];
        #pragma unroll 8
        for (int d = 0; d < 64; d++) s = fmaf(ssS[pt*64 + d], Ws2s[d*3 + l], s);
        g_fw[(p0+pt)*3 + l] = 1.f / (1.f + expf(-s));
    }

    {
        int pt  = tid & 63;
        int grp = tid >> 6;
        unsigned long long accA[8], accB[8];
        #pragma unroll
        for (int u = 0; u < 8; u++) {
            accA[u] = *(const unsigned long long*)(b2v + grp*16 + 2*u);
            accB[u] = 0ull;
        }
        #pragma unroll 4
        for (int d = 0; d < 64; d++) {
            unsigned long long fv2 = pack2(featS[pt*65 + d]);
            const unsigned long long* wa = (const unsigned long long*)(W2s + d*64       + grp*16);
            const unsigned long long* wb = (const unsigned long long*)(W2s + (64+d)*64  + grp*16);
            #pragma unroll
            for (int u = 0; u < 8; u++) {
                accA[u] = ffma2(wa[u], fv2, accA[u]);
                accB[u] = ffma2(wb[u], fv2, accB[u]);
            }
        }
        float2* pA = (float2*)(g_A  + (p0+pt)*64 + grp*16);
        float2* pB = (float2*)(g_Bf + (p0+pt)*64 + grp*16);
        #pragma unroll
        for (int u = 0; u < 8; u++) {
            pA[u] = *(float2*)&accA[u];
            pB[u] = *(float2*)&accB[u];
        }
    }
}

// ---------------------------------------------------------------------------
// K3 (fused): gather+edge-max+fw -> multiT (smem), then fusion MLP.
// Pad 36 (16B-aligned rows) + LDS.128 broadcast input loads: per-kk shared
// wavefronts 8 -> 6 in L1, 6 -> 4 in L2 (crossbar was the binding pipe).
// ---------------------------------------------------------------------------
__global__ void __launch_bounds__(256, 2)
k_fuse(const float* __restrict__ x,
       const float* __restrict__ g2, const float* __restrict__ be2,
       const float* __restrict__ Wf1, const float* __restrict__ bf1,
       const float* __restrict__ gf1, const float* __restrict__ bef1,
       const float* __restrict__ Wf2, const float* __restrict__ bf2,
       const float* __restrict__ gf2, const float* __restrict__ bef2,
       const float* __restrict__ Wf3, const float* __restrict__ bf3,
       float* __restrict__ out)
{
    extern __shared__ float sm[];
    float* multiT = sm;                   // [192][36] = 6912 ; h2T aliases [128][36]
    float* h2T    = sm;
    float* h1T    = sm + 6912;            // [256][36] = 9216
    float* ws     = sm + 16128;           // 2 x 4096
    float* b1S    = sm + 24320;           // 256
    float* g1S    = sm + 24576;           // 256
    float* e1S    = sm + 24832;           // 256
    float* b2S    = sm + 25088;           // 128
    float* g2S    = sm + 25216;           // 128
    float* e2S    = sm + 25344;           // 128
    float* wf3S   = sm + 25472;           // 384
    float* fwS    = sm + 25856;           // 96
    float* bf3S   = sm + 25952;           // 4
    int*   idxS   = (int*)(sm + 25956);   // 256
    float* g2v    = sm + 26212;           // 64
    float* be2v   = sm + 26276;           // 64 -> total 26340 floats

    const int tid  = threadIdx.x;
    const int lane = tid & 31;
    const int wrp  = tid >> 5;
    const int p0   = blockIdx.x * PTB;
    const int pg   = wrp & 3;
    const int oh   = wrp >> 2;
    const int pbase = pg * 8;

    { b1S[tid]=bf1[tid]; g1S[tid]=gf1[tid]; e1S[tid]=bef1[tid]; }
    if (tid < 128) { b2S[tid]=bf2[tid]; g2S[tid]=gf2[tid]; e2S[tid]=bef2[tid]; }
    for (int i = tid; i < 384; i += 256) wf3S[i] = Wf3[i];
    if (tid < 96)  fwS[tid]=g_fw[p0*3 + tid];
    if (tid < 3)   bf3S[tid]=bf3[tid];
    idxS[tid] = g_idx[p0*8 + tid];
    if (tid < 64) { g2v[tid]=g2[tid]; be2v[tid]=be2[tid]; }
    __syncthreads();

    {
        int pt = tid & 31, grp = tid >> 5, d0 = grp * 8;
        int p = p0 + pt;
        int bbase = p & ~(NN - 1);
        float4 a0 = *(const float4*)(g_A + p*64 + d0);
        float4 a1 = *(const float4*)(g_A + p*64 + d0 + 4);
        float4 gg0 = *(const float4*)(g2v + d0);
        float4 gg1 = *(const float4*)(g2v + d0 + 4);
        float4 ee0 = *(const float4*)(be2v + d0);
        float4 ee1 = *(const float4*)(be2v + d0 + 4);
        float m[8];
        #pragma unroll
        for (int u = 0; u < 8; u++) m[u] = -3.4e38f;
        #pragma unroll
        for (int k = 0; k < 8; k++) {
            int j = idxS[pt*8 + k];
            const float4* bp = (const float4*)(g_Bf + (bbase + j)*64 + d0);
            float4 v0 = bp[0], v1 = bp[1];
            m[0] = fmaxf(m[0], leaky(fmaf(a0.x + v0.x, gg0.x, ee0.x)));
            m[1] = fmaxf(m[1], leaky(fmaf(a0.y + v0.y, gg0.y, ee0.y)));
            m[2] = fmaxf(m[2], leaky(fmaf(a0.z + v0.z, gg0.z, ee0.z)));
            m[3] = fmaxf(m[3], leaky(fmaf(a0.w + v0.w, gg0.w, ee0.w)));
            m[4] = fmaxf(m[4], leaky(fmaf(a1.x + v1.x, gg1.x, ee1.x)));
            m[5] = fmaxf(m[5], leaky(fmaf(a1.y + v1.y, gg1.y, ee1.y)));
            m[6] = fmaxf(m[6], leaky(fmaf(a1.z + v1.z, gg1.z, ee1.z)));
            m[7] = fmaxf(m[7], leaky(fmaf(a1.w + v1.w, gg1.w, ee1.w)));
        }
        float fw0 = fwS[pt*3], fw1 = fwS[pt*3+1], fw2 = fwS[pt*3+2];
        #pragma unroll
        for (int dd = 0; dd < 8; dd++) {
            multiT[(d0+dd)*36 + pt]        = m[dd] * fw0;
            multiT[(64+d0+dd)*36 + pt]     = m[dd] * fw1;
            multiT[(128+d0+dd)*36 + pt]    = m[dd] * fw2;
        }
    }
    __syncthreads();

    // ---- layer 1: 192 -> 256 ----
    unsigned long long acc[4][4];
    #pragma unroll
    for (int i = 0; i < 4; i++)
        #pragma unroll
        for (int q = 0; q < 4; q++) acc[i][q] = 0ull;

    #pragma unroll
    for (int u = 0; u < 4; u++)
        *(float4*)(ws + (tid + u*256)*4) = *(const float4*)(Wf1 + (tid + u*256)*4);
    __syncthreads();

    for (int c = 0; c < 12; c++) {
        float4 pf[4];
        if (c < 11) {
            #pragma unroll
            for (int u = 0; u < 4; u++)
                pf[u] = *(const float4*)(Wf1 + (c+1)*4096 + (tid + u*256)*4);
        }
        const float* wb = ws + (c & 1) * 4096;
        #pragma unroll
        for (int kk = 0; kk < 16; kk++) {
            const ulonglong2* mrow =
                (const ulonglong2*)(multiT + (c*16 + kk)*36 + pbase);
            ulonglong2 m01 = mrow[0], m23 = mrow[1];
            unsigned long long in0 = m01.x, in1 = m01.y, in2 = m23.x, in3 = m23.y;
            const float* wrow = wb + kk*256 + oh*128 + lane;
            #pragma unroll
            for (int i = 0; i < 4; i++) {
                unsigned long long wp = pack2(wrow[32*i]);
                acc[i][0] = ffma2(in0, wp, acc[i][0]);
                acc[i][1] = ffma2(in1, wp, acc[i][1]);
                acc[i][2] = ffma2(in2, wp, acc[i][2]);
                acc[i][3] = ffma2(in3, wp, acc[i][3]);
            }
        }
        if (c < 11) {
            float* wd = ws + ((c+1) & 1) * 4096;
            #pragma unroll
            for (int u = 0; u < 4; u++)
                *(float4*)(wd + (tid + u*256)*4) = pf[u];
        }
        __syncthreads();
    }
    #pragma unroll
    for (int i = 0; i < 4; i++) {
        int o = oh*128 + 32*i + lane;
        float bb = b1S[o], gg = g1S[o], ee = e1S[o];
        #pragma unroll
        for (int q = 0; q < 4; q++) {
            float2 v = *(float2*)&acc[i][q];
            float2 hv;
            hv.x = leaky(fmaf(v.x + bb, gg, ee));
            hv.y = leaky(fmaf(v.y + bb, gg, ee));
            *(float2*)(h1T + o*36 + pbase + 2*q) = hv;
        }
    }
    __syncthreads();

    // ---- layer 2: 256 -> 128 ----
    unsigned long long a2[2][4];
    #pragma unroll
    for (int i = 0; i < 2; i++)
        #pragma unroll
        for (int q = 0; q < 4; q++) a2[i][q] = 0ull;

    #pragma unroll
    for (int u = 0; u < 2; u++)
        *(float4*)(ws + (tid + u*256)*4) = *(const float4*)(Wf2 + (tid + u*256)*4);
    __syncthreads();

    for (int c = 0; c < 16; c++) {
        float4 pf[2];
        if (c < 15) {
            #pragma unroll
            for (int u = 0; u < 2; u++)
                pf[u] = *(const float4*)(Wf2 + (c+1)*2048 + (tid + u*256)*4);
        }
        const float* wb = ws + (c & 1) * 2048;
        #pragma unroll
        for (int kk = 0; kk < 16; kk++) {
            const ulonglong2* hrow =
                (const ulonglong2*)(h1T + (c*16 + kk)*36 + pbase);
            ulonglong2 h01 = hrow[0], h23 = hrow[1];
            unsigned long long in0 = h01.x, in1 = h01.y, in2 = h23.x, in3 = h23.y;
            const float* wrow = wb + kk*128 + oh*64 + lane;
            #pragma unroll
            for (int i = 0; i < 2; i++) {
                unsigned long long wp = pack2(wrow[32*i]);
                a2[i][0] = ffma2(in0, wp, a2[i][0]);
                a2[i][1] = ffma2(in1, wp, a2[i][1]);
                a2[i][2] = ffma2(in2, wp, a2[i][2]);
                a2[i][3] = ffma2(in3, wp, a2[i][3]);
            }
        }
        if (c < 15) {
            float* wd = ws + ((c+1) & 1) * 2048;
            #pragma unroll
            for (int u = 0; u < 2; u++)
                *(float4*)(wd + (tid + u*256)*4) = pf[u];
        }
        __syncthreads();
    }
    #pragma unroll
    for (int i = 0; i < 2; i++) {
        int o = oh*64 + 32*i + lane;
        float bb = b2S[o], gg = g2S[o], ee = e2S[o];
        #pragma unroll
        for (int q = 0; q < 4; q++) {
            float2 v = *(float2*)&a2[i][q];
            float2 hv;
            hv.x = leaky(fmaf(v.x + bb, gg, ee));
            hv.y = leaky(fmaf(v.y + bb, gg, ee));
            *(float2*)(h2T + o*36 + pbase + 2*q) = hv;
        }
    }
    __syncthreads();

    // ---- layer 3: 128 -> 3 + residual ----
    if (tid < 96) {
        int pt = tid / 3, cc = tid - pt*3;
        float s0 = 0.f, s1 = 0.f;
        #pragma unroll 8
        for (int k = 0; k < 128; k += 2) {
            s0 = fmaf(h2T[k*36 + pt],     wf3S[k*3 + cc],     s0);
            s1 = fmaf(h2T[(k+1)*36 + pt], wf3S[(k+1)*3 + cc], s1);
        }
        int gp = p0 + pt;
        out[gp*3 + cc] = fmaf(0.1f, (s0 + s1) + bf3S[cc], x[gp*3 + cc]);
    }
}

// ---------------------------------------------------------------------------
extern "C" void kernel_launch(void* const* d_in, const int* in_sizes, int n_in,
                              void* d_out, int out_size)
{
    const float* x    = (const float*)d_in[0];
    const float* W1   = (const float*)d_in[1];
    const float* b1   = (const float*)d_in[2];
    const float* g1   = (const float*)d_in[3];
    const float* be1  = (const float*)d_in[4];
    const float* W2   = (const float*)d_in[5];
    const float* b2   = (const float*)d_in[6];
    const float* g2   = (const float*)d_in[7];
    const float* be2  = (const float*)d_in[8];
    const float* Ws1  = (const float*)d_in[9];
    const float* bs1  = (const float*)d_in[10];
    const float* Ws2  = (const float*)d_in[11];
    const float* bs2  = (const float*)d_in[12];
    const float* Wf1  = (const float*)d_in[13];
    const float* bf1  = (const float*)d_in[14];
    const float* gf1  = (const float*)d_in[15];
    const float* bef1 = (const float*)d_in[16];
    const float* Wf2  = (const float*)d_in[17];
    const float* bf2  = (const float*)d_in[18];
    const float* gf2  = (const float*)d_in[19];
    const float* bef2 = (const float*)d_in[20];
    const float* Wf3  = (const float*)d_in[21];
    const float* bf3  = (const float*)d_in[22];
    float* out = (float*)d_out;

    const int SM1 = 17540 * 4;   // k_pk shared bytes (prep layout dominates)
    const int SM4 = 26340 * 4;   // k_fuse shared bytes (~105.4KB)

    cudaFuncSetAttribute(k_pk,   cudaFuncAttributeMaxDynamicSharedMemorySize, SM1);
    cudaFuncSetAttribute(k_fuse, cudaFuncAttributeMaxDynamicSharedMemorySize, SM4);

    k_pk<<<NKNNB + NPREPB, 256, SM1>>>(x, W1, b1, g1, be1, W2, b2,
                                       Ws1, bs1, Ws2, bs2);
    k_fuse<<<PTS/PTB, 256, SM4>>>(x, g2, be2, Wf1, bf1, gf1, bef1,
                                  Wf2, bf2, gf2, bef2, Wf3, bf3, out);
}